// round 4
// baseline (speedup 1.0000x reference)
#include <cuda_runtime.h>

#define T_DIM 1024
#define B_DIM 128
#define H_DIM 256
#define CHUNK 64
#define NCHUNK 16                 // 16 * 64 = 1024 steps
#define NCTA 148
#define NWORK (NCTA - 1)          // 147 worker CTAs
#define NWARPW (NWORK * 8)        // 1176 worker warps
#define NTHW (NWORK * 256)        // 37632 worker threads

// Scratch (__device__ globals; allocation-free rule).
__device__ __align__(16) float g_xdot[(T_DIM + 8) * B_DIM * 4]; // [t][b][4], padded
__device__ __align__(16) float g_h[T_DIM * B_DIM];              // [t][b]
__device__ __align__(16) float g_c[B_DIM];
__device__ int g_xdone[NCHUNK];
__device__ int g_rdone;

// ---- fast math helpers -----------------------------------------------------
__device__ __forceinline__ float sin_ap(float x) {
    float r; asm("sin.approx.f32 %0, %1;" : "=f"(r) : "f"(x)); return r;
}
__device__ __forceinline__ float rcp_ap(float x) {
    float r; asm("rcp.approx.f32 %0, %1;" : "=f"(r) : "f"(x)); return r;
}
// sigmoid(s), |s|<=1, deg-4 in u=s^2, abs err ~2e-6. FMA pipe only.
__device__ __forceinline__ float sigm_poly(float s) {
    const float A0 = 0.25f, A1 = -2.0833333e-2f, A2 = 2.0833333e-3f,
                A3 = -2.1081349e-4f, A4 = 2.1356790e-5f;
    float u  = s * s;
    float u2 = u * u;
    float b0 = fmaf(A1, u, A0);
    float b1 = fmaf(A3, u, A2);
    float p  = fmaf(fmaf(A4, u2, b1), u2, b0);
    return fmaf(s, p, 0.5f);
}
// tanh continued fraction depth 4, |x|<=1 (err ~5e-6). One rcp.
__device__ __forceinline__ float tanh_p4(float x) {
    float u = x * x;
    float n = fmaf(10.0f, u, 105.0f);
    float d = fmaf(u, u + 45.0f, 105.0f);
    return x * n * rcp_ap(d);
}
// tanh continued fraction depth 6, |x|<=2.2 (err ~3e-6; |c|<=2.07 provably). One rcp.
__device__ __forceinline__ float tanh_p6(float x) {
    float u  = x * x;
    float u2 = u * u;
    float n  = fmaf(fmaf(21.0f, u, 1260.0f), u, 10395.0f);
    float d  = fmaf(u2, u + 210.0f, fmaf(4725.0f, u, 10395.0f));
    return x * n * rcp_ap(d);
}

__device__ __forceinline__ void waitGe(const int* p, int v) {
    while (*(volatile const int*)p < v) __nanosleep(64);
}

// ---- zero the cross-CTA flags (runs before the fused kernel each call) -----
__global__ void k_zero() {
    int i = threadIdx.x;
    if (i < NCHUNK) g_xdone[i] = 0;
    if (i == NCHUNK) g_rdone = 0;
}

// ---- fused persistent kernel ----------------------------------------------
__global__ __launch_bounds__(256, 1) void k_fused(const float* __restrict__ in,
                                                  const float* __restrict__ Wt,
                                                  const float* __restrict__ bias,
                                                  float* __restrict__ out) {
    const int cta = blockIdx.x;
    const int tid = threadIdx.x;
    const int lane = tid & 31;

    if (cta == 0) {
        // ========== recurrence CTA: 8 warps, 16 active lanes each ==========
        // (2 warps per SMSP -> cross-warp latency hiding of the serial chain)
        const int wid = tid >> 5;
        // whsum[g] computed redundantly per warp with all 32 lanes
        float wh[4];
#pragma unroll
        for (int g = 0; g < 4; g++) {
            const float* wr = Wt + g * 512 + 256;
            float s = 0.f;
#pragma unroll
            for (int k = 0; k < 8; k++) s += wr[lane + k * 32];
#pragma unroll
            for (int o = 16; o; o >>= 1) s += __shfl_xor_sync(0xffffffffu, s, o);
            wh[g] = s;
        }
        const float w0 = wh[0], w1 = wh[1], w2 = wh[2], w3 = wh[3];

        const bool act = lane < 16;
        const int b = wid * 16 + (lane & 15);      // 8*16 = 128 chains
        const float4* xd4 = reinterpret_cast<const float4*>(g_xdot);

        if (tid == 0) waitGe(&g_xdone[0], NWORK);
        __syncthreads();

        float lf = 0.f, li = 0.f, lg = 0.f, lo = 0.f;
        float4 buf[4];
        if (act) {
            float4 x0 = xd4[b];
            lf = x0.x; li = x0.y; lg = x0.z; lo = x0.w;
#pragma unroll
            for (int k = 0; k < 4; k++) buf[k] = xd4[(k + 1) * B_DIM + b];
        }

        float c = 0.f;
        for (int ch = 0; ch < NCHUNK; ch++) {
            int c2 = (ch + 1 < NCHUNK) ? ch + 1 : NCHUNK - 1;
            if (tid == 0) { waitGe(&g_xdone[ch], NWORK); waitGe(&g_xdone[c2], NWORK); }
            __syncthreads();

            const int t0 = ch * CHUNK;
#pragma unroll 4
            for (int t = t0; t < t0 + CHUNK; t++) {
                float4 nxt = buf[t & 3];
                if (act) buf[t & 3] = xd4[(t + 5) * B_DIM + b];  // prefetch, off-chain

                float sf = sin_ap(lf);
                float si = sin_ap(li);
                float sg = sin_ap(lg);
                float so = sin_ap(lo);
                float f  = sigm_poly(sf);
                float i_ = sigm_poly(si);
                float gg = tanh_p4(sg);
                float o  = sigm_poly(so);
                c = fmaf(f, c, i_ * gg);
                float wo0 = w0 * o, wo1 = w1 * o, wo2 = w2 * o, wo3 = w3 * o;
                float tc = tanh_p6(c);
                lf = fmaf(wo0, tc, nxt.x);
                li = fmaf(wo1, tc, nxt.y);
                lg = fmaf(wo2, tc, nxt.z);
                lo = fmaf(wo3, tc, nxt.w);
                if (act) g_h[t * B_DIM + b] = o * tc;            // coalesced STG.32
            }
            if (ch == NCHUNK - 1 && act) g_c[b] = c;
            __threadfence();
            __syncthreads();
            if (tid == 0) *(volatile int*)&g_rdone = (ch + 1) * CHUNK;
        }
        return;
    }

    // ================= worker CTAs: xdot then bcast =================
    __shared__ float4 sW[4][64];
    for (int i = tid; i < 4 * 64; i += 256) {
        int g = i >> 6, cc = i & 63;
        sW[g][cc] = reinterpret_cast<const float4*>(Wt)[g * 128 + cc];
    }
    __syncthreads();

    const int warp = tid >> 5;
    const int wg = (cta - 1) * 8 + warp;          // 0..1175
    const float bv = (lane < 4) ? bias[lane] : 0.f;
    const float4* in4 = reinterpret_cast<const float4*>(in);
    const unsigned FULL = 0xffffffffu;

    for (int ch = 0; ch < NCHUNK; ch++) {
        const int pe = (ch + 1) * CHUNK * B_DIM;
        for (int p = ch * CHUNK * B_DIM + wg; p < pe; p += NWARPW) {
            const float4* src = in4 + (long)p * 64;
            float4 a0 = src[lane];
            float4 a1 = src[lane + 32];
            float s[4];
#pragma unroll
            for (int g = 0; g < 4; g++) {
                float4 w = sW[g][lane];
                float t = a0.x * w.x + a0.y * w.y + a0.z * w.z + a0.w * w.w;
                w = sW[g][lane + 32];
                t += a1.x * w.x + a1.y * w.y + a1.z * w.z + a1.w * w.w;
                s[g] = t;
            }
            // packed 6-shuffle reduction of 4 sums
            bool b0 = lane & 1;
            float t01 = b0 ? s[0] : s[1];
            float k01 = b0 ? s[1] : s[0];
            k01 += __shfl_xor_sync(FULL, t01, 1);
            float t23 = b0 ? s[2] : s[3];
            float k23 = b0 ? s[3] : s[2];
            k23 += __shfl_xor_sync(FULL, t23, 1);
            bool b1 = lane & 2;
            float tv = b1 ? k01 : k23;
            float kv = b1 ? k23 : k01;
            kv += __shfl_xor_sync(FULL, tv, 2);
            kv += __shfl_xor_sync(FULL, kv, 4);
            kv += __shfl_xor_sync(FULL, kv, 8);
            kv += __shfl_xor_sync(FULL, kv, 16);
            if (lane < 4) g_xdot[p * 4 + lane] = kv + bv;
        }
        __threadfence();
        __syncthreads();
        if (tid == 0) atomicAdd(&g_xdone[ch], 1);
    }

    // ---- bcast phase: trail the recurrence ----
    float4* out4 = reinterpret_cast<float4*>(out);
    const int widx = (cta - 1) * 256 + tid;
    const long S4 = (long)T_DIM * B_DIM * H_DIM / 4;   // 8388608
    for (int ch = 0; ch < NCHUNK; ch++) {
        if (tid == 0) waitGe(&g_rdone, (ch + 1) * CHUNK);
        __syncthreads();
        const long base = (long)ch * CHUNK * (B_DIM * H_DIM / 4);
        const long end  = base + (long)CHUNK * (B_DIM * H_DIM / 4);
        for (long i = base + widx; i < end; i += NTHW) {
            int t = (int)(i >> 13);            // 8192 float4 per t
            int b = (int)(i >> 6) & 127;
            float v = g_h[t * B_DIM + b];      // warp-uniform load
            out4[i] = make_float4(v, v, v, v);
        }
    }
    // tails: hx (== h at t=1023) and cx
    for (long i = S4 + widx; i < S4 + 16384; i += NTHW) {
        int r = (int)(i - S4);
        float v;
        if (r < 8192) v = g_h[(T_DIM - 1) * B_DIM + (r >> 6)];
        else          v = g_c[(r - 8192) >> 6];
        out4[i] = make_float4(v, v, v, v);
    }
}

extern "C" void kernel_launch(void* const* d_in, const int* in_sizes, int n_in,
                              void* d_out, int out_size) {
    const float* in   = (const float*)d_in[0];   // [T,B,D]
    const float* Wt   = (const float*)d_in[1];   // [4, D+H]
    const float* bias = (const float*)d_in[2];   // [4]
    // d_in[3] (qw) mathematically has no effect on the output.
    float* out = (float*)d_out;

    k_zero<<<1, 32>>>();
    k_fused<<<NCTA, 256>>>(in, Wt, bias, out);
}